// round 13
// baseline (speedup 1.0000x reference)
#include <cuda_runtime.h>
#include <cuda_fp16.h>
#include <math.h>

// ---------------- problem constants ----------------
#define IMG     256
#define VIEWS   128
#define NDET    512
#define NS      364          // ceil(2R/STEP)+1, R = 256*sqrt(2)/2
#define SIDf    750.0f
#define SDDf    1250.0f
#define DET_ELT 1.2f
#define Rf      181.01933598375618f   // 256*sqrt(2)/2

// ---------------- packed padded images (fp16, full bilinear stencil / cell) ----
#define PAD 4
#define PW  272
#define PWf 272.0f
#define CPAIRS 136            // PW/2 cell-pairs per row in pack

__device__ uint4  g_pack [PW * PW];
__device__ uint4  g_packT[PW * PW];
__device__ float2 g_view[VIEWS];      // (cos beta, sin beta)

__device__ __forceinline__ float imgval(const float* x, int b, int i, int j) {
    if (i < 0 || i >= IMG || j < 0 || j >= IMG) return 0.f;
    return x[b * IMG * IMG + i * IMG + j];
}

// One thread builds TWO adjacent cells (c, c+1), c even, for BOTH layouts.
__global__ void pack_kernel(const float* __restrict__ x) {
    int idx = blockIdx.x * blockDim.x + threadIdx.x;
    if (idx < VIEWS) {
        float beta = (float)((double)(2.8125 * (double)idx) * 0.017453292519943295);
        g_view[idx] = make_float2(cosf(beta), sinf(beta));
    }
    if (idx >= PW * CPAIRS) return;
    int r  = idx / CPAIRS;
    int c  = (idx % CPAIRS) * 2;
    int i  = r - PAD, j = c - PAD;     // j even

    float vv[2][2][3];                 // [row][batch][col]
    if (i >= 0 && i <= IMG - 2 && j >= 0 && j <= IMG - 4) {
        #pragma unroll
        for (int rr = 0; rr < 2; ++rr)
            #pragma unroll
            for (int b = 0; b < 2; ++b) {
                const float* p = x + b * IMG * IMG + (i + rr) * IMG + j;
                float2 lo = *reinterpret_cast<const float2*>(p);  // 8B aligned
                vv[rr][b][0] = lo.x;
                vv[rr][b][1] = lo.y;
                vv[rr][b][2] = p[2];
            }
    } else {
        #pragma unroll
        for (int rr = 0; rr < 2; ++rr)
            #pragma unroll
            for (int b = 0; b < 2; ++b)
                #pragma unroll
                for (int cc = 0; cc < 3; ++cc)
                    vv[rr][b][cc] = imgval(x, b, i + rr, j + cc);
    }

    __half hv[2][2][3];
    #pragma unroll
    for (int rr = 0; rr < 2; ++rr)
        #pragma unroll
        for (int b = 0; b < 2; ++b)
            #pragma unroll
            for (int cc = 0; cc < 3; ++cc)
                hv[rr][b][cc] = __float2half_rn(vv[rr][b][cc]);

    __half n0[8] = { hv[0][0][0], hv[0][1][0], hv[0][0][1], hv[0][1][1],
                     hv[1][0][0], hv[1][1][0], hv[1][0][1], hv[1][1][1] };
    __half n1[8] = { hv[0][0][1], hv[0][1][1], hv[0][0][2], hv[0][1][2],
                     hv[1][0][1], hv[1][1][1], hv[1][0][2], hv[1][1][2] };
    g_pack[r * PW + c]     = *reinterpret_cast<uint4*>(n0);
    g_pack[r * PW + c + 1] = *reinterpret_cast<uint4*>(n1);

    __half t0[8] = { hv[0][0][0], hv[0][1][0], hv[1][0][0], hv[1][1][0],
                     hv[0][0][1], hv[0][1][1], hv[1][0][1], hv[1][1][1] };
    __half t1[8] = { hv[0][0][1], hv[0][1][1], hv[1][0][1], hv[1][1][1],
                     hv[0][0][2], hv[0][1][2], hv[1][0][2], hv[1][1][2] };
    g_packT[c * PW + r]       = *reinterpret_cast<uint4*>(t0);
    g_packT[(c + 1) * PW + r] = *reinterpret_cast<uint4*>(t1);
}

// ---------------- main projection kernel ----------------
// Grid = 8 pairs x 128 views = 1024 blocks (single balanced wave). Block
// handles detector groups g and g+8 of one view (same layout both halves ->
// warm L1). Warp = 16 detectors x 2 ADJACENT sample-phases (lane = d*2+k):
// each warp-load's footprint is ~11.5px x 1px instead of a 23px line,
// cutting L1 wavefronts ~35% for all view angles. Thread k integrates
// samples cs+k, cs+k+2, ... of its warp's segment (4 segments per 16-det
// half). A/B pipeline keeps the pair spatially contiguous (samples s..s+3).
#define NSEG 4

__device__ __forceinline__ __half2 bilerp2(uint4 raw, __half2 gu2, __half2 gw2) {
    const __half2* h2 = reinterpret_cast<const __half2*>(&raw);
    __half2 top = __hfma2(gu2, __hsub2(h2[1], h2[0]), h2[0]);
    __half2 bot = __hfma2(gu2, __hsub2(h2[3], h2[2]), h2[2]);
    return __hfma2(gw2, __hsub2(bot, top), top);
}

__global__ void __launch_bounds__(256, 8) fpj_kernel(float* __restrict__ out) {
    const int lane = threadIdx.x & 31;
    const int w    = threadIdx.x >> 5;         // warp 0..7
    const int d    = lane >> 1;                // detector within 16-det half
    const int k    = lane & 1;                 // sample phase 0/1
    const int h2   = w & 1;                    // which 16-det half of the 32
    const int seg  = w >> 1;                   // segment 0..3
    const int v = blockIdx.y;                  // view index

    // view terms (uniform per block)
    float2 cs2 = g_view[v];
    float cb = cs2.x, sb = cs2.y;
    bool trans = fabsf(cb) >= fabsf(sb);
    const uint4* __restrict__ pk = trans ? g_packT : g_pack;

    __shared__ float r0[128];
    __shared__ float r1[128];

    #pragma unroll
    for (int half = 0; half < 2; ++half) {
        int g = blockIdx.x + half * 8;         // detector group 0..15
        int n = g * 32 + h2 * 16 + d;          // detector index

        // ---- geometry (float32 math matching the reference) ----
        float u  = ((float)n - 255.5f) * DET_ELT;  // DET_OFF = 0
        float dx = -SDDf * cb - u * sb;            // det - src
        float dy = -SDDf * sb + u * cb;
        float inv = rsqrtf(dx * dx + dy * dy);
        dx *= inv; dy *= inv;                      // unit ray direction

        const float t0  = SIDf - Rf;
        float jx0 = fmaf(t0, dx, SIDf * cb) + 127.5f;  // jx at s=0
        float iy0 = 127.5f - fmaf(t0, dy, SIDf * sb);  // iy at s=0
        float djx = dx;                                // STEP=1, PIX=1
        float diy = -dy;

        // ---- clip s to where both coords stay in [-1.5, 256.5] ----
        const float LO = -1.5f, HI = 256.5f;
        float slo = 0.f, shi = (float)(NS - 1);
        {
            float rx = __fdividef(1.f, djx);
            float ry = __fdividef(1.f, diy);
            float s1 = (LO - jx0) * rx, s2 = (HI - jx0) * rx;
            slo = fmaxf(slo, fminf(s1, s2));
            shi = fminf(shi, fmaxf(s1, s2));
            s1 = (LO - iy0) * ry; s2 = (HI - iy0) * ry;
            slo = fmaxf(slo, fminf(s1, s2));
            shi = fminf(shi, fmaxf(s1, s2));
        }
        int is = (int)fminf(fmaxf(ceilf(slo),  0.f), (float)(NS - 1));
        int ie = (int)fminf(fmaxf(floorf(shi), -1.f), (float)(NS - 1));

        // fast coord = contiguous axis of the chosen layout; fold PAD into origin
        float u0 = (trans ? iy0 : jx0) + (float)PAD;
        float du =  trans ? diy : djx;
        float w0 = (trans ? jx0 : iy0) + (float)PAD;
        float dw =  trans ? djx : diy;

        // ---- this warp's segment; this thread's phase within it ----
        int len  = ie - is + 1;
        int per  = (len + NSEG - 1) >> 2;          // ceil(len/4)
        int cs   = is + seg * per;
        int ce   = cs + per - 1;
        if (ce > ie) ce = ie;
        int lenS = ce - cs + 1;
        int cnt  = (lenS - k + 1) >> 1;            // this thread's sample count

        float fu = fmaf((float)(cs + k), du, u0);
        float fw = fmaf((float)(cs + k), dw, w0);
        float du2 = du + du, dw2 = dw + dw;

        float acc0 = 0.f, acc1 = 0.f;

        #pragma unroll 2
        for (; cnt >= 2; cnt -= 2) {
            float ufA = floorf(fu),  wfA = floorf(fw);
            float fuB = fu + du2,    fwB = fw + dw2;
            float ufB = floorf(fuB), wfB = floorf(fwB);

            int baseA = (int)fmaf(wfA, PWf, ufA);  // exact: integers < 2^24
            int baseB = (int)fmaf(wfB, PWf, ufB);

            uint4 rawA = pk[baseA];
            uint4 rawB = pk[baseB];

            __half2 guA = __float2half2_rn(fu  - ufA);
            __half2 gwA = __float2half2_rn(fw  - wfA);
            __half2 guB = __float2half2_rn(fuB - ufB);
            __half2 gwB = __float2half2_rn(fwB - wfB);

            __half2 rA = bilerp2(rawA, guA, gwA);
            __half2 rB = bilerp2(rawB, guB, gwB);
            float2 f = __half22float2(__hadd2(rA, rB));
            acc0 += f.x;
            acc1 += f.y;

            fu = fuB + du2;
            fw = fwB + dw2;
        }
        if (cnt > 0) {                             // odd tail
            float uf = floorf(fu), wf = floorf(fw);
            uint4 raw = pk[(int)fmaf(wf, PWf, uf)];
            float2 f = __half22float2(bilerp2(raw,
                           __float2half2_rn(fu - uf), __float2half2_rn(fw - wf)));
            acc0 += f.x;
            acc1 += f.y;
        }

        // ---- reduce: 2 phases via shuffle, then 4 segments via smem ----
        acc0 += __shfl_xor_sync(0xFFFFFFFFu, acc0, 1);
        acc1 += __shfl_xor_sync(0xFFFFFFFFu, acc1, 1);

        if (half) __syncthreads();                 // protect smem reuse
        if (k == 0) {
            int di = seg * 32 + h2 * 16 + d;       // [seg][det-in-32]
            r0[di] = acc0;
            r1[di] = acc1;
        }
        __syncthreads();

        if (threadIdx.x < 32) {
            int n2 = g * 32 + threadIdx.x;
            float s0 = r0[threadIdx.x]      + r0[threadIdx.x + 32]
                     + r0[threadIdx.x + 64] + r0[threadIdx.x + 96];
            float s1 = r1[threadIdx.x]      + r1[threadIdx.x + 32]
                     + r1[threadIdx.x + 64] + r1[threadIdx.x + 96];
            out[v * NDET + n2]                = s0; // STEP = 1.0 scale no-op
            out[VIEWS * NDET + v * NDET + n2] = s1;
        }
    }
}

// ---------------- launch ----------------
extern "C" void kernel_launch(void* const* d_in, const int* in_sizes, int n_in,
                              void* d_out, int out_size) {
    const float* x = (const float*)d_in[0];
    float* out = (float*)d_out;
    (void)in_sizes; (void)n_in; (void)out_size;

    pack_kernel<<<(PW * CPAIRS + 255) / 256, 256>>>(x);
    fpj_kernel<<<dim3(8, VIEWS), 256>>>(out);
}

// round 14
// speedup vs baseline: 1.3818x; 1.3818x over previous
#include <cuda_runtime.h>
#include <cuda_fp16.h>
#include <math.h>

// ---------------- problem constants ----------------
#define IMG     256
#define VIEWS   128
#define NDET    512
#define NS      364          // ceil(2R/STEP)+1, R = 256*sqrt(2)/2
#define SIDf    750.0f
#define SDDf    1250.0f
#define DET_ELT 1.2f
#define Rf      181.01933598375618f   // 256*sqrt(2)/2

// ---------------- packed padded images (fp16, full bilinear stencil / cell) ----
#define PAD 4
#define PW  272
#define PWf 272.0f
#define CPAIRS 136            // PW/2 cell-pairs per row in pack

__device__ uint4  g_pack [PW * PW];
__device__ uint4  g_packT[PW * PW];
__device__ float2 g_view[VIEWS];      // (cos beta, sin beta)

__device__ __forceinline__ float imgval(const float* x, int b, int i, int j) {
    if (i < 0 || i >= IMG || j < 0 || j >= IMG) return 0.f;
    return x[b * IMG * IMG + i * IMG + j];
}

// One thread builds TWO adjacent cells (c, c+1), c even, for BOTH layouts.
__global__ void pack_kernel(const float* __restrict__ x) {
    int idx = blockIdx.x * blockDim.x + threadIdx.x;
    if (idx < VIEWS) {
        float beta = (float)((double)(2.8125 * (double)idx) * 0.017453292519943295);
        g_view[idx] = make_float2(cosf(beta), sinf(beta));
    }
    if (idx >= PW * CPAIRS) return;
    int r  = idx / CPAIRS;
    int c  = (idx % CPAIRS) * 2;
    int i  = r - PAD, j = c - PAD;     // j even

    float vv[2][2][3];                 // [row][batch][col]
    if (i >= 0 && i <= IMG - 2 && j >= 0 && j <= IMG - 4) {
        #pragma unroll
        for (int rr = 0; rr < 2; ++rr)
            #pragma unroll
            for (int b = 0; b < 2; ++b) {
                const float* p = x + b * IMG * IMG + (i + rr) * IMG + j;
                float2 lo = *reinterpret_cast<const float2*>(p);  // 8B aligned
                vv[rr][b][0] = lo.x;
                vv[rr][b][1] = lo.y;
                vv[rr][b][2] = p[2];
            }
    } else {
        #pragma unroll
        for (int rr = 0; rr < 2; ++rr)
            #pragma unroll
            for (int b = 0; b < 2; ++b)
                #pragma unroll
                for (int cc = 0; cc < 3; ++cc)
                    vv[rr][b][cc] = imgval(x, b, i + rr, j + cc);
    }

    __half hv[2][2][3];
    #pragma unroll
    for (int rr = 0; rr < 2; ++rr)
        #pragma unroll
        for (int b = 0; b < 2; ++b)
            #pragma unroll
            for (int cc = 0; cc < 3; ++cc)
                hv[rr][b][cc] = __float2half_rn(vv[rr][b][cc]);

    __half n0[8] = { hv[0][0][0], hv[0][1][0], hv[0][0][1], hv[0][1][1],
                     hv[1][0][0], hv[1][1][0], hv[1][0][1], hv[1][1][1] };
    __half n1[8] = { hv[0][0][1], hv[0][1][1], hv[0][0][2], hv[0][1][2],
                     hv[1][0][1], hv[1][1][1], hv[1][0][2], hv[1][1][2] };
    g_pack[r * PW + c]     = *reinterpret_cast<uint4*>(n0);
    g_pack[r * PW + c + 1] = *reinterpret_cast<uint4*>(n1);

    __half t0[8] = { hv[0][0][0], hv[0][1][0], hv[1][0][0], hv[1][1][0],
                     hv[0][0][1], hv[0][1][1], hv[1][0][1], hv[1][1][1] };
    __half t1[8] = { hv[0][0][1], hv[0][1][1], hv[1][0][1], hv[1][1][1],
                     hv[0][0][2], hv[0][1][2], hv[1][0][2], hv[1][1][2] };
    g_packT[c * PW + r]       = *reinterpret_cast<uint4*>(t0);
    g_packT[(c + 1) * PW + r] = *reinterpret_cast<uint4*>(t1);
}

// ---------------- main projection kernel ----------------
// 1-D grid of 1024 blocks (single balanced wave). bid -> (v = bid & 127,
// g = bid >> 7): CLC places consecutive bids on consecutive SMs, so each
// SM's ~7 resident blocks carry views spaced 20 indices = 56.25 deg =
// 11.25 deg modulo the 45-deg L1-cost period -> per-SM total work averages
// over the view-cost spectrum (fixes the same-view-per-SM imbalance of the
// 2-D grid without R12's locality loss).
// Block = one view, detector groups g and g+8 (cost-balanced pair, same
// layout both halves -> warm L1). 32 detectors x CHUNK=8 segments;
// 1 LDG.128/sample (full stencil, both batches); incremental coords;
// half2 SIMD lerps; fast clip divides.
#define CHUNK 8

__device__ __forceinline__ __half2 bilerp2(uint4 raw, __half2 gu2, __half2 gw2) {
    const __half2* h2 = reinterpret_cast<const __half2*>(&raw);
    __half2 top = __hfma2(gu2, __hsub2(h2[1], h2[0]), h2[0]);
    __half2 bot = __hfma2(gu2, __hsub2(h2[3], h2[2]), h2[2]);
    return __hfma2(gw2, __hsub2(bot, top), top);
}

__global__ void __launch_bounds__(256, 8) fpj_kernel(float* __restrict__ out) {
    const int lane  = threadIdx.x & 31;        // detector within group
    const int chunk = threadIdx.x >> 5;        // 0..7 segment id
    const int v  = blockIdx.x & 127;           // view index
    const int g0 = blockIdx.x >> 7;            // detector-group base 0..7

    // view terms (uniform per block)
    float2 cs2 = g_view[v];
    float cb = cs2.x, sb = cs2.y;
    bool trans = fabsf(cb) >= fabsf(sb);
    const uint4* __restrict__ pk = trans ? g_packT : g_pack;

    __shared__ float r0[256];
    __shared__ float r1[256];

    #pragma unroll
    for (int half = 0; half < 2; ++half) {
        int g = g0 + half * 8;                 // detector group 0..15
        int n = g * 32 + lane;                 // detector index

        // ---- geometry (float32 math matching the reference) ----
        float u  = ((float)n - 255.5f) * DET_ELT;  // DET_OFF = 0
        float dx = -SDDf * cb - u * sb;            // det - src
        float dy = -SDDf * sb + u * cb;
        float inv = rsqrtf(dx * dx + dy * dy);
        dx *= inv; dy *= inv;                      // unit ray direction

        const float t0  = SIDf - Rf;
        float jx0 = fmaf(t0, dx, SIDf * cb) + 127.5f;  // jx at s=0
        float iy0 = 127.5f - fmaf(t0, dy, SIDf * sb);  // iy at s=0
        float djx = dx;                                // STEP=1, PIX=1
        float diy = -dy;

        // ---- clip s to where both coords stay in [-1.5, 256.5] ----
        // fast divides: boundary has a 0.5px zero-contribution margin and PAD
        // slack, so few-ulp clip error is value-neutral.
        const float LO = -1.5f, HI = 256.5f;
        float slo = 0.f, shi = (float)(NS - 1);
        {
            float rx = __fdividef(1.f, djx);
            float ry = __fdividef(1.f, diy);
            float s1 = (LO - jx0) * rx, s2 = (HI - jx0) * rx;
            slo = fmaxf(slo, fminf(s1, s2));
            shi = fminf(shi, fmaxf(s1, s2));
            s1 = (LO - iy0) * ry; s2 = (HI - iy0) * ry;
            slo = fmaxf(slo, fminf(s1, s2));
            shi = fminf(shi, fmaxf(s1, s2));
        }
        int is = (int)fminf(fmaxf(ceilf(slo),  0.f), (float)(NS - 1));
        int ie = (int)fminf(fmaxf(floorf(shi), -1.f), (float)(NS - 1));

        // fast coord = contiguous axis of the chosen layout; fold PAD into origin
        float u0 = (trans ? iy0 : jx0) + (float)PAD;
        float du =  trans ? diy : djx;
        float w0 = (trans ? jx0 : iy0) + (float)PAD;
        float dw =  trans ? djx : diy;

        // ---- this thread's sub-segment ----
        int len = ie - is + 1;
        int per = (len + CHUNK - 1) >> 3;          // ceil(len/8)
        int cs  = is + chunk * per;
        int ce  = cs + per - 1;
        if (ce > ie) ce = ie;
        int cnt = ce - cs + 1;                     // may be <= 0

        float fu = fmaf((float)cs, du, u0);
        float fw = fmaf((float)cs, dw, w0);

        float acc0 = 0.f, acc1 = 0.f;

        #pragma unroll 2
        for (; cnt >= 2; cnt -= 2) {
            float ufA = floorf(fu),  wfA = floorf(fw);
            float fuB = fu + du,     fwB = fw + dw;
            float ufB = floorf(fuB), wfB = floorf(fwB);

            int baseA = (int)fmaf(wfA, PWf, ufA);  // exact: integers < 2^24
            int baseB = (int)fmaf(wfB, PWf, ufB);

            uint4 rawA = pk[baseA];
            uint4 rawB = pk[baseB];

            __half2 guA = __float2half2_rn(fu  - ufA);
            __half2 gwA = __float2half2_rn(fw  - wfA);
            __half2 guB = __float2half2_rn(fuB - ufB);
            __half2 gwB = __float2half2_rn(fwB - wfB);

            __half2 rA = bilerp2(rawA, guA, gwA);
            __half2 rB = bilerp2(rawB, guB, gwB);
            float2 f = __half22float2(__hadd2(rA, rB));
            acc0 += f.x;
            acc1 += f.y;

            fu = fuB + du;
            fw = fwB + dw;
        }
        if (cnt > 0) {                             // odd tail
            float uf = floorf(fu), wf = floorf(fw);
            uint4 raw = pk[(int)fmaf(wf, PWf, uf)];
            float2 f = __half22float2(bilerp2(raw,
                           __float2half2_rn(fu - uf), __float2half2_rn(fw - wf)));
            acc0 += f.x;
            acc1 += f.y;
        }

        // ---- reduce the CHUNK segment partials per detector ----
        if (half) __syncthreads();                 // protect smem reuse
        r0[threadIdx.x] = acc0;
        r1[threadIdx.x] = acc1;
        __syncthreads();

        if (chunk == 0) {
            float s0 = 0.f, s1 = 0.f;
            #pragma unroll
            for (int c = 0; c < CHUNK; ++c) {
                s0 += r0[lane + 32 * c];
                s1 += r1[lane + 32 * c];
            }
            out[v * NDET + n]                = s0; // STEP = 1.0 scale is a no-op
            out[VIEWS * NDET + v * NDET + n] = s1;
        }
    }
}

// ---------------- launch ----------------
extern "C" void kernel_launch(void* const* d_in, const int* in_sizes, int n_in,
                              void* d_out, int out_size) {
    const float* x = (const float*)d_in[0];
    float* out = (float*)d_out;
    (void)in_sizes; (void)n_in; (void)out_size;

    pack_kernel<<<(PW * CPAIRS + 255) / 256, 256>>>(x);
    fpj_kernel<<<1024, 256>>>(out);
}